// round 16
// baseline (speedup 1.0000x reference)
#include <cuda_runtime.h>
#include <cuda_bf16.h>
#include <math.h>

#define NB 256
#define BATCHN 128
#define NSTEPS 100
#define MAXEV 5
#define HID 64
#define NTH 512
#define NWARP (NTH/32)
#define SEGCAP 388
#define CAPC 4096
#define MARGIN 1.0f

#define BAR_SYNC(id,cnt)   asm volatile("bar.sync %0, %1;"   :: "r"(id), "r"(cnt) : "memory")

__device__ __forceinline__ float silu_f(float x) {
    return __fdividef(x, 1.0f + __expf(-x));
}

// lexicographic 64-bit min across full warp via 2x REDUX.MIN.u32
__device__ __forceinline__ unsigned long long warp_min_key(unsigned long long key) {
    unsigned hi = (unsigned)(key >> 32), lo = (unsigned)key;
    unsigned mh = __reduce_min_sync(0xFFFFFFFFu, hi);
    unsigned cl = (hi == mh) ? lo : 0xFFFFFFFFu;
    unsigned ml = __reduce_min_sync(0xFFFFFFFFu, cl);
    return ((unsigned long long)mh << 32) | ml;
}

__device__ __forceinline__ void fold_ball_key(unsigned long long& key, int p, float d2, float two_r) {
    float gap = sqrtf(d2) - two_r;
    unsigned gu = __float_as_uint(gap);
    gu = (gu & 0x80000000u) ? ~gu : (gu | 0x80000000u);   // monotone float->uint
    unsigned long long k = ((unsigned long long)gu << 32) | (unsigned)p;
    if (k < key) key = k;
}

__global__ __launch_bounds__(NTH, 1)
void hybrid_rollout(const float* __restrict__ g_state,
                    const float* __restrict__ g_radii,
                    const float* __restrict__ g_W1,
                    const float* __restrict__ g_b1,
                    const float* __restrict__ g_W2,
                    const float* __restrict__ g_b2,
                    const float* __restrict__ g_W3,
                    const float* __restrict__ g_b3,
                    float* __restrict__ g_out)
{
    __shared__ float4 own[NB];                 // this block's batch element (AoS: apply path only)
    __shared__ float2 sPos[NB];                // batch-0 positions (SoA)
    __shared__ float2 sVel[NB];                // batch-0 velocities (SoA)
    __shared__ float4 w2q[16*HID];             // w2q[k4*HID+o] = W2[o][4k4..4k4+3]
    __shared__ float w1s[2*HID];
    __shared__ float b1s[HID], b2s[HID], w3s[HID];
    __shared__ float4 h1q[2*16];
    __shared__ float h2buf[2*HID];
    __shared__ unsigned long long redK[NWARP];
    __shared__ float vmaxW[NWARP];
    __shared__ int nCandW[NWARP];
    __shared__ int candList[NWARP*SEGCAP];     // rebuild scratch: per-warp segments
    __shared__ __align__(16) int candC[CAPC];  // compact balanced list (scan target)
    __shared__ int sNC;                        // compact list length
    __shared__ int sVmax2i;
    __shared__ float sMotion;
    __shared__ int sOverflow;
    __shared__ float sb3, srr;

    const int tid  = threadIdx.x;
    const int bidx = blockIdx.x;
    const int i0   = tid & (NB-1);
    const int half = tid >> 8;
    const int lane = tid & 31;
    const int warp = tid >> 5;

    // ---- setup ----
    if (tid < NB) {
        float4 v = reinterpret_cast<const float4*>(g_state)[bidx*NB + tid];
        own[tid] = v;
        float4 c = reinterpret_cast<const float4*>(g_state)[tid];
        sPos[tid] = make_float2(c.x, c.y);
        sVel[tid] = make_float2(c.z, c.w);
        reinterpret_cast<float4*>(g_out)[bidx*NB + tid] = v;
    }
    for (int q = tid; q < 16*HID; q += NTH) {
        int o = q & 63, k4 = q >> 6;
        const float* src = g_W2 + o*HID + k4*4;
        w2q[q] = make_float4(src[0], src[1], src[2], src[3]);
    }
    if (tid < 2*HID) w1s[tid] = g_W1[tid];
    if (tid < HID) { b1s[tid] = g_b1[tid]; b2s[tid] = g_b2[tid]; w3s[tid] = g_W3[tid]; }
    if (tid == 0) {
        sb3 = g_b3[0]; srr = g_radii[0];
        sMotion = 1e30f; sVmax2i = 0; sOverflow = 0; sNC = 0;
    }
    __syncthreads();

    const float rr    = srr;
    const float two_r = rr + rr;
    const float cut   = two_r + 0.051f;        // exact narrow cutoff (gap>0.05 -> done)
    const float c2    = cut * cut;
    const float cute  = cut + MARGIN;          // broad-phase cutoff
    const float c2e   = cute * cute;
    const float b3v   = sb3;

    unsigned long long wkCache = ~0ull;        // cached min wall key of ball i0 (half==0)
    bool wkDirty = true;

    for (int s = 0; s < NSTEPS; ++s) {
        const float t_s = (float)s * 0.05f;
        const float t_e = t_s + 0.05f;
        float t_c = t_s;
        wkDirty = true;                        // step-end integration moved everything

        for (int ev = 0; ev < MAXEV; ++ev) {
            // ================= P0: detection =================
            const bool rebuild = (sOverflow != 0) || (sMotion >= MARGIN);
            const float2 mp = sPos[i0];
            const float2 mv = sVel[i0];
            unsigned long long key = ~0ull;

            if (rebuild) {
                // warp-max of speed^2 via REDUX (non-negative floats: uint-monotone)
                {
                    unsigned mu = __reduce_max_sync(0xFFFFFFFFu,
                                    __float_as_uint(mv.x*mv.x + mv.y*mv.y));
                    if (lane == 0) vmaxW[warp] = __uint_as_float(mu);
                }
                int cnt = 0;
                const int segBase = warp * SEGCAP;
                for (int d = 1 + half; d <= 127; d += 2) {
                    int j = (i0 + d) & (NB-1);
                    float2 pj = sPos[j];
                    float dx = pj.x - mp.x, dy = pj.y - mp.y;
                    float d2 = dx*dx + dy*dy;
                    bool push = (d2 <= c2e);
                    unsigned msk = __ballot_sync(0xFFFFFFFFu, push);
                    if (push) {
                        int lo = (i0 < j) ? i0 : j;
                        int hi = (i0 < j) ? j : i0;
                        int p = (lo << 8) | hi;
                        int slot = cnt + __popc(msk & ((1u << lane) - 1u));
                        if (slot < SEGCAP) candList[segBase + slot] = p;
                        if (d2 <= c2) {
                            float2 vj = sVel[j];
                            float dvx = vj.x - mv.x, dvy = vj.y - mv.y;
                            if (dvx*dx + dvy*dy < 0.0f)
                                fold_ball_key(key, p, d2, two_r);
                        }
                    }
                    cnt += __popc(msk);
                }
                if (half == 1 && i0 < 128) {               // d == 128 (warp-uniform)
                    int j = (i0 + 128) & (NB-1);
                    float2 pj = sPos[j];
                    float dx = pj.x - mp.x, dy = pj.y - mp.y;
                    float d2 = dx*dx + dy*dy;
                    bool push = (d2 <= c2e);
                    unsigned msk = __ballot_sync(0xFFFFFFFFu, push);
                    if (push) {
                        int p = (i0 << 8) | j;                 // i0 < j always here
                        int slot = cnt + __popc(msk & ((1u << lane) - 1u));
                        if (slot < SEGCAP) candList[segBase + slot] = p;
                        if (d2 <= c2) {
                            float2 vj = sVel[j];
                            float dvx = vj.x - mv.x, dvy = vj.y - mv.y;
                            if (dvx*dx + dvy*dy < 0.0f)
                                fold_ball_key(key, p, d2, two_r);
                        }
                    }
                    cnt += __popc(msk);
                }
                if (lane == 0) nCandW[warp] = cnt;
            } else {
                // event-time narrow scan: uniform single sweep over compact list
                const int n4 = (sNC + 3) & ~3;
                for (int e4 = tid * 4; e4 < n4; e4 += NTH * 4) {
                    int4 pk = *reinterpret_cast<const int4*>(&candC[e4]);
                    #pragma unroll
                    for (int i = 0; i < 4; ++i) {
                        int p = (&pk.x)[i];
                        int lo = p >> 8, hi = p & 255;
                        float2 pl = sPos[lo], ph = sPos[hi];
                        float dx = ph.x - pl.x, dy = ph.y - pl.y;
                        float d2 = dx*dx + dy*dy;
                        if (d2 <= c2) {
                            float2 vl = sVel[lo], vh = sVel[hi];
                            float dvx = vh.x - vl.x, dvy = vh.y - vl.y;
                            if (dvx*dx + dvy*dy < 0.0f)
                                fold_ball_key(key, p, d2, two_r);
                        }
                    }
                }
            }

            // wall candidates (cached min-of-4 key; recompute only when ball i0 changed)
            if (half == 0) {
                if (wkDirty) {
                    unsigned long long wkmin = ~0ull;
                    float gs[4]; bool vs[4];
                    gs[0] = mp.x - rr;          vs[0] = mv.x < 0.0f;
                    gs[1] = 10.0f - mp.x - rr;  vs[1] = mv.x > 0.0f;
                    gs[2] = mp.y - rr;          vs[2] = mv.y < 0.0f;
                    gs[3] = 10.0f - mp.y - rr;  vs[3] = mv.y > 0.0f;
                    #pragma unroll
                    for (int w = 0; w < 4; ++w) {
                        if (vs[w]) {
                            unsigned u = __float_as_uint(gs[w]);
                            u = (u & 0x80000000u) ? ~u : (u | 0x80000000u);
                            unsigned long long k = ((unsigned long long)u << 32) |
                                                   0x80000000u | (unsigned)(i0*4 + w);
                            if (k < wkmin) wkmin = k;
                        }
                    }
                    wkCache = wkmin;
                    wkDirty = false;
                }
                if (wkCache < key) key = wkCache;
            }

            // warp REDUX min -> STS -> BAR -> block REDUX min over 16 slots
            key = warp_min_key(key);
            if (lane == 0) redK[warp] = key;
            __syncthreads();                              // ---- BAR A ----

            if (rebuild) {
                // all warps: compact ragged segments into candC (balanced scan target).
                // Readers of candC/sNC are in LATER iterations, always separated by a
                // full barrier (BAR E / W2 / step-end) -> no extra barrier needed here.
                int off = 0, total = 0;
                #pragma unroll
                for (int w = 0; w < NWARP; ++w) {
                    int c = nCandW[w]; c = (c > SEGCAP) ? SEGCAP : c;
                    off += (w < warp) ? c : 0;
                    total += c;
                }
                int myN = nCandW[warp]; if (myN > SEGCAP) myN = SEGCAP;
                const int segBase = warp * SEGCAP;
                for (int e = lane; e < myN; e += 32) {
                    int dst = off + e;
                    if (dst < CAPC) candC[dst] = candList[segBase + e];
                }
                if (tid == NTH-1) {
                    float vm = vmaxW[0];
                    #pragma unroll
                    for (int w = 1; w < NWARP; ++w) vm = fmaxf(vm, vmaxW[w]);
                    sVmax2i = __float_as_int(vm);
                    int ov = (total > CAPC);
                    #pragma unroll
                    for (int w = 0; w < NWARP; ++w) ov |= (nCandW[w] > SEGCAP);
                    if (ov) sOverflow = 1;
                    sMotion = 0.0f;
                    int tt = (total < CAPC) ? total : CAPC;
                    sNC = tt;
                    int t4 = (tt + 3) & ~3;                // CAPC is a multiple of 4
                    for (int k = tt; k < t4; ++k) candC[k] = 0;  // key-inert sentinel
                }
            }

            key = warp_min_key(redK[lane & (NWARP-1)]);

            const unsigned gHi = (unsigned)(key >> 32);
            if (gHi == 0xFFFFFFFFu) break;                 // no candidates -> done
            unsigned gu = (gHi & 0x80000000u) ? (gHi ^ 0x80000000u) : ~gHi;
            const float gap = __uint_as_float(gu);
            if (gap > 0.05f) break;                        // no_event -> done

            const unsigned lo32 = (unsigned)key;
            const bool is_ball = (lo32 < 0x80000000u);

            // redundant decode + flags on ALL threads
            int iA, iB = 0, wsel = 0;
            float app;
            if (is_ball) {
                iA = (int)((lo32 >> 8) & 255u);
                iB = (int)(lo32 & 255u);
                float2 pi = sPos[iA], pj = sPos[iB];
                float2 vi = sVel[iA], vj = sVel[iB];
                float nx = pj.x - pi.x, ny = pj.y - pi.y;
                float rL = rsqrtf(fmaxf(nx*nx + ny*ny, 1e-30f));
                app = -((vj.x - vi.x)*nx + (vj.y - vi.y)*ny) * rL;
            } else {
                unsigned idx = lo32 & 0x7FFFFFFFu;
                iA = (int)(idx >> 2);
                wsel = (int)(idx & 3u);
                float2 vi = sVel[iA];
                app = fabsf(fmaxf(vi.x, vi.y));
            }
            const float t_ev  = t_c + __fdividef(gap, fmaxf(app, 1e-6f));
            const bool case_a = (gap <= 0.0f);
            const bool case_b = (!case_a) && (app > 1e-6f) && (t_ev < t_e);
            if (!case_a && !case_b) break;                 // done
            const float dte = case_b ? ((t_ev > t_c + 1e-10f) ? (t_ev - t_c) : 0.0f) : 0.0f;
            if (case_b) t_c = t_ev;

            if (is_ball) {
                // warps 0-3: MLP; warps 4-11: integrate (skip iA,iB); thread 511: sMotion
                if (tid < 2*HID) {
                    int sel = tid >> 6, o = tid & (HID-1);
                    float4 si, sj;
                    if (sel) {
                        float2 p1 = sPos[iA], v1 = sVel[iA];
                        float2 p2 = sPos[iB], v2 = sVel[iB];
                        si = make_float4(p1.x, p1.y, v1.x, v1.y);
                        sj = make_float4(p2.x, p2.y, v2.x, v2.y);
                    } else {
                        si = own[iA]; sj = own[iB];
                    }
                    float six = fmaf(si.z, dte, si.x), siy = fmaf(si.w, dte, si.y);
                    float sjx = fmaf(sj.z, dte, sj.x), sjy = fmaf(sj.w, dte, sj.y);
                    float dx = sjx - six, dy = sjy - siy;
                    float d2h = dx*dx + dy*dy;
                    float ri = rsqrtf(fmaxf(d2h, 1e-30f));
                    float dist = fmaxf(d2h * ri, 1e-8f);
                    float nx = dx * ri, ny = dy * ri;
                    float ap = (sj.z - si.z)*nx + (sj.w - si.w)*ny;
                    float pre = dist*w1s[2*o] + ap*w1s[2*o+1] + b1s[o];
                    reinterpret_cast<float*>(h1q)[sel*HID + o] = silu_f(pre);
                    BAR_SYNC(3, 128);                     // h1 ready (warps 0-3)
                    const float4* H = &h1q[sel*16];
                    float a0 = 0.f, a1 = 0.f, a2 = 0.f, a3 = 0.f;
                    #pragma unroll 2
                    for (int k4 = 0; k4 < 16; k4 += 4) {
                        float4 w0 = w2q[(k4+0)*HID + o], hh0 = H[k4+0];
                        a0 = fmaf(w0.x,hh0.x,a0); a0 = fmaf(w0.y,hh0.y,a0);
                        a0 = fmaf(w0.z,hh0.z,a0); a0 = fmaf(w0.w,hh0.w,a0);
                        float4 w1v = w2q[(k4+1)*HID + o], hh1 = H[k4+1];
                        a1 = fmaf(w1v.x,hh1.x,a1); a1 = fmaf(w1v.y,hh1.y,a1);
                        a1 = fmaf(w1v.z,hh1.z,a1); a1 = fmaf(w1v.w,hh1.w,a1);
                        float4 w2v = w2q[(k4+2)*HID + o], hh2 = H[k4+2];
                        a2 = fmaf(w2v.x,hh2.x,a2); a2 = fmaf(w2v.y,hh2.y,a2);
                        a2 = fmaf(w2v.z,hh2.z,a2); a2 = fmaf(w2v.w,hh2.w,a2);
                        float4 w3v = w2q[(k4+3)*HID + o], hh3 = H[k4+3];
                        a3 = fmaf(w3v.x,hh3.x,a3); a3 = fmaf(w3v.y,hh3.y,a3);
                        a3 = fmaf(w3v.z,hh3.z,a3); a3 = fmaf(w3v.w,hh3.w,a3);
                    }
                    float acc = ((b2s[o] + a0) + a1) + (a2 + a3);
                    h2buf[sel*HID + o] = w3s[o] * silu_f(acc);
                    BAR_SYNC(3, 128);                     // h2 ready (warps 0-3)
                    if (warp == 0 || warp == 2) {
                        int sl = warp >> 1;
                        float v = h2buf[sl*HID + lane] + h2buf[sl*HID + 32 + lane];
                        #pragma unroll
                        for (int off2 = 16; off2 > 0; off2 >>= 1)
                            v += __shfl_down_sync(0xFFFFFFFFu, v, off2);
                        if (lane == 0) {
                            float impv = v + b3v;
                            float4 ti, tj;
                            if (sl) {
                                float2 p1 = sPos[iA], v1 = sVel[iA];
                                float2 p2 = sPos[iB], v2 = sVel[iB];
                                ti = make_float4(p1.x, p1.y, v1.x, v1.y);
                                tj = make_float4(p2.x, p2.y, v2.x, v2.y);
                            } else {
                                ti = own[iA]; tj = own[iB];
                            }
                            float tix = fmaf(ti.z, dte, ti.x), tiy = fmaf(ti.w, dte, ti.y);
                            float tjx = fmaf(tj.z, dte, tj.x), tjy = fmaf(tj.w, dte, tj.y);
                            float ddx = tjx - tix, ddy = tjy - tiy;
                            float dd2 = ddx*ddx + ddy*ddy;
                            float rst = rsqrtf(fmaxf(dd2, 1e-30f));
                            // match h1's clamped-dist normalization exactly
                            float dstc = fmaxf(dd2 * rst, 1e-8f);
                            float rdc = __fdividef(1.0f, dstc);
                            float nnx = ddx*rdc, nny = ddy*rdc;
                            float niz = ti.z + impv*nnx, niw = ti.w + impv*nny;
                            float njz = tj.z - impv*nnx, njw = tj.w - impv*nny;
                            if (sl) {
                                sPos[iA] = make_float2(tix, tiy);
                                sPos[iB] = make_float2(tjx, tjy);
                                sVel[iA] = make_float2(niz, niw);
                                sVel[iB] = make_float2(njz, njw);
                                float sp = fmaxf(niz*niz + niw*niw, njz*njz + njw*njw);
                                atomicMax(&sVmax2i, __float_as_int(sp));
                            } else {
                                own[iA] = make_float4(tix, tiy, niz, niw);
                                own[iB] = make_float4(tjx, tjy, njz, njw);
                            }
                        }
                    }
                } else if (tid < 384) {
                    int b = tid - 128;
                    if (dte != 0.0f && b != iA && b != iB) {
                        float4 v = own[b];
                        v.x = fmaf(v.z, dte, v.x); v.y = fmaf(v.w, dte, v.y);
                        own[b] = v;
                        float2 p = sPos[b], vv = sVel[b];
                        sPos[b] = make_float2(fmaf(vv.x, dte, p.x), fmaf(vv.y, dte, p.y));
                    }
                } else if (tid == NTH-1) {
                    sMotion += 2.0f * sqrtf(__int_as_float(sVmax2i)) * dte;
                }
                __syncthreads();                          // ---- BAR E ----
            } else {
                // wall: compute result + integrate (b != iA) pre-barrier; write iA after
                float4 res; float pen = 0.0f;
                if (tid < 2) {
                    float4 si;
                    if (tid) {
                        float2 p1 = sPos[iA], v1 = sVel[iA];
                        si = make_float4(p1.x, p1.y, v1.x, v1.y);
                    } else {
                        si = own[iA];
                    }
                    float six = fmaf(si.z, dte, si.x), siy = fmaf(si.w, dte, si.y);
                    float wnx = 0.0f, wny = 0.0f, wp = 0.0f;
                    if      (wsel == 0) { wnx =  1.0f; }
                    else if (wsel == 1) { wnx = -1.0f; wp = -10.0f; }
                    else if (wsel == 2) { wny =  1.0f; }
                    else                { wny = -1.0f; wp = -10.0f; }
                    float vn  = si.z*wnx + si.w*wny;
                    float nvx = si.z - 2.0f*vn*wnx;
                    float nvy = si.w - 2.0f*vn*wny;
                    float pn  = six*wnx + siy*wny;
                    pen = fmaxf(wp + rr - pn, 0.0f);
                    res = make_float4(six + pen*wnx, siy + pen*wny, nvx, nvy);
                } else if (tid >= 128 && tid < 384) {
                    int b = tid - 128;
                    if (dte != 0.0f && b != iA) {
                        float4 v = own[b];
                        v.x = fmaf(v.z, dte, v.x); v.y = fmaf(v.w, dte, v.y);
                        own[b] = v;
                        float2 p = sPos[b], vv = sVel[b];
                        sPos[b] = make_float2(fmaf(vv.x, dte, p.x), fmaf(vv.y, dte, p.y));
                    }
                }
                __syncthreads();                          // ---- BAR W1 ----
                if (tid < 2) {
                    if (tid) {
                        sPos[iA] = make_float2(res.x, res.y);
                        sVel[iA] = make_float2(res.z, res.w);
                        sMotion += 2.0f * sqrtf(__int_as_float(sVmax2i)) * dte + pen;
                    } else {
                        own[iA] = res;
                    }
                }
                __syncthreads();                          // ---- BAR W2 ----
            }

            // wall-key cache invalidation (ball i0's pos/vel changed?)
            if (half == 0) {
                if (dte != 0.0f || i0 == iA || (is_ball && i0 == iB)) wkDirty = true;
            }
        }  // events

        // ---- step end ----
        __syncthreads();                                  // orders break-path reads vs writes
        const float dte2 = (t_e > t_c + 1e-10f) ? (t_e - t_c) : 0.0f;
        if (tid < NB) {
            float4 v = own[tid];
            v.x = fmaf(v.z, dte2, v.x); v.y = fmaf(v.w, dte2, v.y);
            own[tid] = v;
            float2 p = sPos[tid], vv = sVel[tid];
            sPos[tid] = make_float2(fmaf(vv.x, dte2, p.x), fmaf(vv.y, dte2, p.y));
            reinterpret_cast<float4*>(g_out)[((long)(s+1)*BATCHN + bidx)*NB + tid] = v;
        }
        if (tid == 0)
            sMotion += 2.0f * sqrtf(__int_as_float(sVmax2i)) * dte2;
        __syncthreads();
    }
}

extern "C" void kernel_launch(void* const* d_in, const int* in_sizes, int n_in,
                              void* d_out, int out_size) {
    (void)in_sizes; (void)n_in; (void)out_size;
    hybrid_rollout<<<BATCHN, NTH>>>(
        (const float*)d_in[0], (const float*)d_in[1],
        (const float*)d_in[2], (const float*)d_in[3],
        (const float*)d_in[4], (const float*)d_in[5],
        (const float*)d_in[6], (const float*)d_in[7],
        (float*)d_out);
}